// round 12
// baseline (speedup 1.0000x reference)
#include <cuda_runtime.h>
#include <cuda_bf16.h>

// SparseDualFlow: reference = 100-iter Nesterov proximal loop per element.
// Algebraic collapse (proved R0-R1): the recurrence
//   next_acc  = 0.882*acc + 0.02*flow - 0.01*d
//   next_flow = relu(0.98*flow - 0.882*acc + 0.01*d)
// is linear per element; relu never clips for d>0 (min flow_t = 0.01*d at
// t=1), flow==0 forever for d<=0, and the global convergence flag cannot
// fire before iter ~133 > 100. => flow_100 = K * max(d, 0), K from running
// the exact recurrence once with d=1 (host-side, double).
//
// CONVERGED — FINAL (locked winner, 4x reproduced on identical source:
// kernel 18.18/18.05/18.21/17.54us, dur 21.22/20.96/21.22/22.08us,
// rel_err 5.62e-4 bit-identical every run). Kernel time and dur are
// ANTI-correlated across runs (fastest kernel 17.54us paired with slowest
// dur 22.08us): the dur spread is harness/graph-replay + DVFS variance,
// not kernel behavior. Evidence of the wall:
//  - traffic irreducible: 64MiB in + 64MiB out; 17.54us best => 7.65 TB/s
//    apparent = 96% of 8TB/s HBM spec.
//  - BATCH scan 1/4/8/16 -> 19.2/18.66/18.18/18.08us: saturated; B8 best
//    end-to-end.
//  - occupancy 81%/49%/20% all equal: in-flight-bytes-limited.
//  - grid 16384..1024 identical within 1%.
//  - dur - kernel ~= 3us = harness overhead on a single-launch graph.
// Further mutation = attributing harness noise to kernel changes.

#define BATCH 8

__global__ void sparse_dual_flow_kernel(const float4* __restrict__ in,
                                        float4* __restrict__ out,
                                        float K, int n4) {
    int base = blockIdx.x * (blockDim.x * BATCH) + threadIdx.x;

    if (base + (BATCH - 1) * blockDim.x < n4) {   // fast path (always, n = 2^24)
        float4 v[BATCH];
        #pragma unroll
        for (int k = 0; k < BATCH; ++k)
            v[k] = __ldcs(&in[base + k * blockDim.x]);   // front-batched loads
        #pragma unroll
        for (int k = 0; k < BATCH; ++k) {
            float4 r;
            r.x = fmaxf(K * v[k].x, 0.0f);
            r.y = fmaxf(K * v[k].y, 0.0f);
            r.z = fmaxf(K * v[k].z, 0.0f);
            r.w = fmaxf(K * v[k].w, 0.0f);
            __stcs(&out[base + k * blockDim.x], r);
        }
    } else {
        #pragma unroll
        for (int k = 0; k < BATCH; ++k) {
            int i = base + k * blockDim.x;
            if (i < n4) {
                float4 d = __ldcs(&in[i]);
                float4 r;
                r.x = fmaxf(K * d.x, 0.0f);
                r.y = fmaxf(K * d.y, 0.0f);
                r.z = fmaxf(K * d.z, 0.0f);
                r.w = fmaxf(K * d.w, 0.0f);
                __stcs(&out[i], r);
            }
        }
    }
}

__global__ void sparse_dual_flow_tail(const float* __restrict__ in,
                                      float* __restrict__ out,
                                      float K, int start, int n) {
    int i = start + blockIdx.x * blockDim.x + threadIdx.x;
    if (i < n) out[i] = fmaxf(K * in[i], 0.0f);
}

static float compute_K() {
    // Exact reference recurrence (reference op order) in double with d = 1.
    const double STEP_SIZE = 0.01, MOMENTUM = 0.9;
    double flow = 0.0, acc = 0.0;
    for (int t = 0; t < 100; ++t) {
        double acc_m = MOMENTUM * acc;
        double gradient = 2.0 * (flow - acc_m) - 1.0;  // d = 1
        double next_acc = acc_m + STEP_SIZE * gradient;
        double next_flow = flow - next_acc;
        if (next_flow < 0.0) next_flow = 0.0;
        flow = next_flow;
        acc = next_acc;
    }
    return (float)flow;
}

extern "C" void kernel_launch(void* const* d_in, const int* in_sizes, int n_in,
                              void* d_out, int out_size) {
    const float* dual = (const float*)d_in[0];
    float* out = (float*)d_out;
    int n = in_sizes[0];

    float K = compute_K();  // host-side, baked as kernel arg at capture time

    int n4 = n / 4;
    if (n4 > 0) {
        const int threads = 256;
        int tile = threads * BATCH;
        int blocks = (n4 + tile - 1) / tile;
        sparse_dual_flow_kernel<<<blocks, threads>>>(
            (const float4*)dual, (float4*)out, K, n4);
    }
    int rem = n - n4 * 4;
    if (rem > 0) {
        sparse_dual_flow_tail<<<1, 64>>>(dual, out, K, n4 * 4, n);
    }
}

// round 13
// speedup vs baseline: 1.0381x; 1.0381x over previous
#include <cuda_runtime.h>
#include <cuda_bf16.h>

// SparseDualFlow: reference = 100-iter Nesterov proximal loop per element.
// Algebraic collapse (proved R0-R1): the recurrence
//   next_acc  = 0.882*acc + 0.02*flow - 0.01*d
//   next_flow = relu(0.98*flow - 0.882*acc + 0.01*d)
// is linear per element; relu never clips for d>0 (min flow_t = 0.01*d at
// t=1), flow==0 forever for d<=0, and the global convergence flag cannot
// fire before iter ~133 > 100. => flow_100 = K * max(d, 0), K from running
// the exact recurrence once with d=1 (host-side, double).
//
// CONVERGED — FINAL (locked winner, 5x reproduced on identical source:
// kernel 18.18/18.05/18.21/17.54/21.98us, dur 21.22/20.96/21.22/22.08/25.31,
// rel_err 5.62e-4 bit-identical every run). R12's 21.98us kernel run is a
// throttled-container outlier: HBM fell to 3736 GB/s while every
// rate-relative counter (fma/alu/issue/L1 %) scaled UP proportionally --
// identical SASS against a slower memory clock. Not a kernel effect.
// Evidence of the wall (healthy containers):
//  - traffic irreducible: 64MiB in + 64MiB out; 17.54us best => 7.65 TB/s
//    apparent = 96% of 8TB/s HBM spec.
//  - BATCH scan 1/4/8/16 -> 19.2/18.66/18.18/18.08us: saturated; B8 best.
//  - occupancy 81%/49%/20% all equal: in-flight-bytes-limited.
//  - grid 16384..1024 identical within 1%.
//  - dur - kernel ~= 3us = harness overhead on a single-launch graph.
// Mutating in response to container-state variance = fitting noise.

#define BATCH 8

__global__ void sparse_dual_flow_kernel(const float4* __restrict__ in,
                                        float4* __restrict__ out,
                                        float K, int n4) {
    int base = blockIdx.x * (blockDim.x * BATCH) + threadIdx.x;

    if (base + (BATCH - 1) * blockDim.x < n4) {   // fast path (always, n = 2^24)
        float4 v[BATCH];
        #pragma unroll
        for (int k = 0; k < BATCH; ++k)
            v[k] = __ldcs(&in[base + k * blockDim.x]);   // front-batched loads
        #pragma unroll
        for (int k = 0; k < BATCH; ++k) {
            float4 r;
            r.x = fmaxf(K * v[k].x, 0.0f);
            r.y = fmaxf(K * v[k].y, 0.0f);
            r.z = fmaxf(K * v[k].z, 0.0f);
            r.w = fmaxf(K * v[k].w, 0.0f);
            __stcs(&out[base + k * blockDim.x], r);
        }
    } else {
        #pragma unroll
        for (int k = 0; k < BATCH; ++k) {
            int i = base + k * blockDim.x;
            if (i < n4) {
                float4 d = __ldcs(&in[i]);
                float4 r;
                r.x = fmaxf(K * d.x, 0.0f);
                r.y = fmaxf(K * d.y, 0.0f);
                r.z = fmaxf(K * d.z, 0.0f);
                r.w = fmaxf(K * d.w, 0.0f);
                __stcs(&out[i], r);
            }
        }
    }
}

__global__ void sparse_dual_flow_tail(const float* __restrict__ in,
                                      float* __restrict__ out,
                                      float K, int start, int n) {
    int i = start + blockIdx.x * blockDim.x + threadIdx.x;
    if (i < n) out[i] = fmaxf(K * in[i], 0.0f);
}

static float compute_K() {
    // Exact reference recurrence (reference op order) in double with d = 1.
    const double STEP_SIZE = 0.01, MOMENTUM = 0.9;
    double flow = 0.0, acc = 0.0;
    for (int t = 0; t < 100; ++t) {
        double acc_m = MOMENTUM * acc;
        double gradient = 2.0 * (flow - acc_m) - 1.0;  // d = 1
        double next_acc = acc_m + STEP_SIZE * gradient;
        double next_flow = flow - next_acc;
        if (next_flow < 0.0) next_flow = 0.0;
        flow = next_flow;
        acc = next_acc;
    }
    return (float)flow;
}

extern "C" void kernel_launch(void* const* d_in, const int* in_sizes, int n_in,
                              void* d_out, int out_size) {
    const float* dual = (const float*)d_in[0];
    float* out = (float*)d_out;
    int n = in_sizes[0];

    float K = compute_K();  // host-side, baked as kernel arg at capture time

    int n4 = n / 4;
    if (n4 > 0) {
        const int threads = 256;
        int tile = threads * BATCH;
        int blocks = (n4 + tile - 1) / tile;
        sparse_dual_flow_kernel<<<blocks, threads>>>(
            (const float4*)dual, (float4*)out, K, n4);
    }
    int rem = n - n4 * 4;
    if (rem > 0) {
        sparse_dual_flow_tail<<<1, 64>>>(dual, out, K, n4 * 4, n);
    }
}

// round 15
// speedup vs baseline: 1.1236x; 1.0824x over previous
#include <cuda_runtime.h>
#include <cuda_bf16.h>

// SparseDualFlow: reference = 100-iter Nesterov proximal loop per element.
// Algebraic collapse (proved R0-R1): the recurrence
//   next_acc  = 0.882*acc + 0.02*flow - 0.01*d
//   next_flow = relu(0.98*flow - 0.882*acc + 0.01*d)
// is linear per element; relu never clips for d>0 (min flow_t = 0.01*d at
// t=1), flow==0 forever for d<=0, and the global convergence flag cannot
// fire before iter ~133 > 100. => flow_100 = K * max(d, 0), K from running
// the exact recurrence once with d=1 (host-side, double).
//
// CONVERGED — FINAL (locked winner, 6x reproduced on identical source;
// R14 was a broker infra failure, the 5th of the session, proven
// uncorrelated with kernel content):
// kernel {17.54,18.05,18.18,18.21,18.27,21.98}us,
// dur    {20.96,21.22,21.22,22.08,24.38,25.31}us,
// rel_err 5.62e-4 bit-identical every run.
// Kernel time tight (+/-2% on healthy containers); dur-kernel gap varies
// 2.9-6.1us, uncorrelated with kernel time = harness graph-replay /
// clock-state overhead on a single-launch graph.
// Evidence of the wall (healthy containers):
//  - traffic irreducible: 64MiB in + 64MiB out; 17.54us best => 7.65 TB/s
//    apparent = 96% of 8TB/s HBM spec.
//  - BATCH scan 1/4/8/16 -> 19.2/18.66/18.18/18.08us: saturated; B8 best.
//  - occupancy 81%/49%/20% all equal: in-flight-bytes-limited.
//  - grid 16384..1024 identical within 1%.
// Mutating in response to infra/harness variance = fitting noise.

#define BATCH 8

__global__ void sparse_dual_flow_kernel(const float4* __restrict__ in,
                                        float4* __restrict__ out,
                                        float K, int n4) {
    int base = blockIdx.x * (blockDim.x * BATCH) + threadIdx.x;

    if (base + (BATCH - 1) * blockDim.x < n4) {   // fast path (always, n = 2^24)
        float4 v[BATCH];
        #pragma unroll
        for (int k = 0; k < BATCH; ++k)
            v[k] = __ldcs(&in[base + k * blockDim.x]);   // front-batched loads
        #pragma unroll
        for (int k = 0; k < BATCH; ++k) {
            float4 r;
            r.x = fmaxf(K * v[k].x, 0.0f);
            r.y = fmaxf(K * v[k].y, 0.0f);
            r.z = fmaxf(K * v[k].z, 0.0f);
            r.w = fmaxf(K * v[k].w, 0.0f);
            __stcs(&out[base + k * blockDim.x], r);
        }
    } else {
        #pragma unroll
        for (int k = 0; k < BATCH; ++k) {
            int i = base + k * blockDim.x;
            if (i < n4) {
                float4 d = __ldcs(&in[i]);
                float4 r;
                r.x = fmaxf(K * d.x, 0.0f);
                r.y = fmaxf(K * d.y, 0.0f);
                r.z = fmaxf(K * d.z, 0.0f);
                r.w = fmaxf(K * d.w, 0.0f);
                __stcs(&out[i], r);
            }
        }
    }
}

__global__ void sparse_dual_flow_tail(const float* __restrict__ in,
                                      float* __restrict__ out,
                                      float K, int start, int n) {
    int i = start + blockIdx.x * blockDim.x + threadIdx.x;
    if (i < n) out[i] = fmaxf(K * in[i], 0.0f);
}

static float compute_K() {
    // Exact reference recurrence (reference op order) in double with d = 1.
    const double STEP_SIZE = 0.01, MOMENTUM = 0.9;
    double flow = 0.0, acc = 0.0;
    for (int t = 0; t < 100; ++t) {
        double acc_m = MOMENTUM * acc;
        double gradient = 2.0 * (flow - acc_m) - 1.0;  // d = 1
        double next_acc = acc_m + STEP_SIZE * gradient;
        double next_flow = flow - next_acc;
        if (next_flow < 0.0) next_flow = 0.0;
        flow = next_flow;
        acc = next_acc;
    }
    return (float)flow;
}

extern "C" void kernel_launch(void* const* d_in, const int* in_sizes, int n_in,
                              void* d_out, int out_size) {
    const float* dual = (const float*)d_in[0];
    float* out = (float*)d_out;
    int n = in_sizes[0];

    float K = compute_K();  // host-side, baked as kernel arg at capture time

    int n4 = n / 4;
    if (n4 > 0) {
        const int threads = 256;
        int tile = threads * BATCH;
        int blocks = (n4 + tile - 1) / tile;
        sparse_dual_flow_kernel<<<blocks, threads>>>(
            (const float4*)dual, (float4*)out, K, n4);
    }
    int rem = n - n4 * 4;
    if (rem > 0) {
        sparse_dual_flow_tail<<<1, 64>>>(dual, out, K, n4 * 4, n);
    }
}

// round 16
// speedup vs baseline: 1.1736x; 1.0445x over previous
#include <cuda_runtime.h>
#include <cuda_bf16.h>

// SparseDualFlow: reference = 100-iter Nesterov proximal loop per element.
// Algebraic collapse (proved R0-R1): the recurrence
//   next_acc  = 0.882*acc + 0.02*flow - 0.01*d
//   next_flow = relu(0.98*flow - 0.882*acc + 0.01*d)
// is linear per element; relu never clips for d>0 (min flow_t = 0.01*d at
// t=1), flow==0 forever for d<=0, and the global convergence flag cannot
// fire before iter ~133 > 100. => flow_100 = K * max(d, 0), K from running
// the exact recurrence once with d=1 (host-side, double).
//
// CONVERGED — FINAL (locked winner, 7x reproduced on identical source):
// kernel {17.54,18.05,18.05,18.18,18.21,18.27,21.98}us,
// dur    {20.96,21.22,21.22,22.08,22.53,24.38,25.31}us,
// rel_err 5.62e-4 bit-identical every run.
// Kernel sigma ~0.25us on healthy containers (one throttled outlier, R12);
// dur-kernel gap varies 2.9-6.1us, uncorrelated with kernel time =
// harness graph-replay / clock-state overhead on a single-launch graph
// (tail kernel never fires for n=2^24).
// Evidence of the wall (healthy containers):
//  - traffic irreducible: 64MiB in + 64MiB out; 17.54us best => 7.65 TB/s
//    apparent = 96% of 8TB/s HBM spec.
//  - BATCH scan 1/4/8/16 -> 19.2/18.66/18.18/18.08us: saturated; B8 best.
//  - occupancy 81%/49%/20% all equal: in-flight-bytes-limited.
//  - grid 16384..1024 identical within 1%.
// Zero identified mechanism remains; mutation = fitting noise.

#define BATCH 8

__global__ void sparse_dual_flow_kernel(const float4* __restrict__ in,
                                        float4* __restrict__ out,
                                        float K, int n4) {
    int base = blockIdx.x * (blockDim.x * BATCH) + threadIdx.x;

    if (base + (BATCH - 1) * blockDim.x < n4) {   // fast path (always, n = 2^24)
        float4 v[BATCH];
        #pragma unroll
        for (int k = 0; k < BATCH; ++k)
            v[k] = __ldcs(&in[base + k * blockDim.x]);   // front-batched loads
        #pragma unroll
        for (int k = 0; k < BATCH; ++k) {
            float4 r;
            r.x = fmaxf(K * v[k].x, 0.0f);
            r.y = fmaxf(K * v[k].y, 0.0f);
            r.z = fmaxf(K * v[k].z, 0.0f);
            r.w = fmaxf(K * v[k].w, 0.0f);
            __stcs(&out[base + k * blockDim.x], r);
        }
    } else {
        #pragma unroll
        for (int k = 0; k < BATCH; ++k) {
            int i = base + k * blockDim.x;
            if (i < n4) {
                float4 d = __ldcs(&in[i]);
                float4 r;
                r.x = fmaxf(K * d.x, 0.0f);
                r.y = fmaxf(K * d.y, 0.0f);
                r.z = fmaxf(K * d.z, 0.0f);
                r.w = fmaxf(K * d.w, 0.0f);
                __stcs(&out[i], r);
            }
        }
    }
}

__global__ void sparse_dual_flow_tail(const float* __restrict__ in,
                                      float* __restrict__ out,
                                      float K, int start, int n) {
    int i = start + blockIdx.x * blockDim.x + threadIdx.x;
    if (i < n) out[i] = fmaxf(K * in[i], 0.0f);
}

static float compute_K() {
    // Exact reference recurrence (reference op order) in double with d = 1.
    const double STEP_SIZE = 0.01, MOMENTUM = 0.9;
    double flow = 0.0, acc = 0.0;
    for (int t = 0; t < 100; ++t) {
        double acc_m = MOMENTUM * acc;
        double gradient = 2.0 * (flow - acc_m) - 1.0;  // d = 1
        double next_acc = acc_m + STEP_SIZE * gradient;
        double next_flow = flow - next_acc;
        if (next_flow < 0.0) next_flow = 0.0;
        flow = next_flow;
        acc = next_acc;
    }
    return (float)flow;
}

extern "C" void kernel_launch(void* const* d_in, const int* in_sizes, int n_in,
                              void* d_out, int out_size) {
    const float* dual = (const float*)d_in[0];
    float* out = (float*)d_out;
    int n = in_sizes[0];

    float K = compute_K();  // host-side, baked as kernel arg at capture time

    int n4 = n / 4;
    if (n4 > 0) {
        const int threads = 256;
        int tile = threads * BATCH;
        int blocks = (n4 + tile - 1) / tile;
        sparse_dual_flow_kernel<<<blocks, threads>>>(
            (const float4*)dual, (float4*)out, K, n4);
    }
    int rem = n - n4 * 4;
    if (rem > 0) {
        sparse_dual_flow_tail<<<1, 64>>>(dual, out, K, n4 * 4, n);
    }
}

// round 17
// speedup vs baseline: 1.2095x; 1.0306x over previous
#include <cuda_runtime.h>
#include <cuda_bf16.h>

// SparseDualFlow: reference = 100-iter Nesterov proximal loop per element.
// Algebraic collapse (proved R0-R1): the recurrence
//   next_acc  = 0.882*acc + 0.02*flow - 0.01*d
//   next_flow = relu(0.98*flow - 0.882*acc + 0.01*d)
// is linear per element; relu never clips for d>0 (min flow_t = 0.01*d at
// t=1), flow==0 forever for d<=0, and the global convergence flag cannot
// fire before iter ~133 > 100. => flow_100 = K * max(d, 0), K from running
// the exact recurrence once with d=1 (host-side, double).
//
// CONVERGED — FINAL (locked winner, 8x reproduced on identical source):
// kernel {17.54,18.05,18.05,18.18,18.21,18.27,18.27,21.98}us,
// dur    {20.96,21.22,21.22,21.57,22.08,22.53,24.38,25.31}us,
// rel_err 5.62e-4 bit-identical every run.
// Kernel sigma ~0.25us on healthy containers (one throttled outlier, R12);
// dur-kernel gap varies 2.9-6.1us, uncorrelated with kernel time =
// harness graph-replay / clock-state overhead on a single-launch graph
// (tail kernel never fires for n=2^24).
// Evidence of the wall (healthy containers):
//  - traffic irreducible: 64MiB in + 64MiB out; 17.54us best => 7.65 TB/s
//    apparent = 96% of 8TB/s HBM spec.
//  - BATCH scan 1/4/8/16 -> 19.2/18.66/18.18/18.08us: saturated; B8 best.
//  - occupancy 81%/49%/20% all equal: in-flight-bytes-limited.
//  - grid 16384..1024 identical within 1%.
// Zero identified mechanism remains; mutation = fitting noise.

#define BATCH 8

__global__ void sparse_dual_flow_kernel(const float4* __restrict__ in,
                                        float4* __restrict__ out,
                                        float K, int n4) {
    int base = blockIdx.x * (blockDim.x * BATCH) + threadIdx.x;

    if (base + (BATCH - 1) * blockDim.x < n4) {   // fast path (always, n = 2^24)
        float4 v[BATCH];
        #pragma unroll
        for (int k = 0; k < BATCH; ++k)
            v[k] = __ldcs(&in[base + k * blockDim.x]);   // front-batched loads
        #pragma unroll
        for (int k = 0; k < BATCH; ++k) {
            float4 r;
            r.x = fmaxf(K * v[k].x, 0.0f);
            r.y = fmaxf(K * v[k].y, 0.0f);
            r.z = fmaxf(K * v[k].z, 0.0f);
            r.w = fmaxf(K * v[k].w, 0.0f);
            __stcs(&out[base + k * blockDim.x], r);
        }
    } else {
        #pragma unroll
        for (int k = 0; k < BATCH; ++k) {
            int i = base + k * blockDim.x;
            if (i < n4) {
                float4 d = __ldcs(&in[i]);
                float4 r;
                r.x = fmaxf(K * d.x, 0.0f);
                r.y = fmaxf(K * d.y, 0.0f);
                r.z = fmaxf(K * d.z, 0.0f);
                r.w = fmaxf(K * d.w, 0.0f);
                __stcs(&out[i], r);
            }
        }
    }
}

__global__ void sparse_dual_flow_tail(const float* __restrict__ in,
                                      float* __restrict__ out,
                                      float K, int start, int n) {
    int i = start + blockIdx.x * blockDim.x + threadIdx.x;
    if (i < n) out[i] = fmaxf(K * in[i], 0.0f);
}

static float compute_K() {
    // Exact reference recurrence (reference op order) in double with d = 1.
    const double STEP_SIZE = 0.01, MOMENTUM = 0.9;
    double flow = 0.0, acc = 0.0;
    for (int t = 0; t < 100; ++t) {
        double acc_m = MOMENTUM * acc;
        double gradient = 2.0 * (flow - acc_m) - 1.0;  // d = 1
        double next_acc = acc_m + STEP_SIZE * gradient;
        double next_flow = flow - next_acc;
        if (next_flow < 0.0) next_flow = 0.0;
        flow = next_flow;
        acc = next_acc;
    }
    return (float)flow;
}

extern "C" void kernel_launch(void* const* d_in, const int* in_sizes, int n_in,
                              void* d_out, int out_size) {
    const float* dual = (const float*)d_in[0];
    float* out = (float*)d_out;
    int n = in_sizes[0];

    float K = compute_K();  // host-side, baked as kernel arg at capture time

    int n4 = n / 4;
    if (n4 > 0) {
        const int threads = 256;
        int tile = threads * BATCH;
        int blocks = (n4 + tile - 1) / tile;
        sparse_dual_flow_kernel<<<blocks, threads>>>(
            (const float4*)dual, (float4*)out, K, n4);
    }
    int rem = n - n4 * 4;
    if (rem > 0) {
        sparse_dual_flow_tail<<<1, 64>>>(dual, out, K, n4 * 4, n);
    }
}